// round 11
// baseline (speedup 1.0000x reference)
#include <cuda_runtime.h>
#include <cuda_fp16.h>
#include <math.h>
#include <stdint.h>

// B=4, S=1024, D=1024, H=16, DH=64 -> BH=64 heads, per-head Q/K/V = [1024,64] contiguous
#define M_QKV   4096
#define DIM     1024
#define NHEADS  64
#define SEQ     1024
#define HDIM    64
#define SCALE   0.03125f      // D^-0.5
#define LN_EPS  1e-5f

#define SSTR    20            // scores smem stride (BK=16 path)
#define QSTR    36            // qkv/pv smem stride (BK=32 path): 36%32==4 -> conflict-free
#define VSTR    72            // V tile stride: 72%32==8 -> conflict-free
#define NTILES  8

#define QKV_SMEM_FLOATS (4 * 128 * QSTR)          // 2 bufs x 2 mats x 128 rows
#define QKV_SMEM_BYTES  (QKV_SMEM_FLOATS * 4)     // 73,728 B

// -------------------- scratch (allocation-free: __device__ globals) --------------------
__device__ float  g_q[M_QKV * DIM];
__device__ float  g_k[M_QKV * DIM];
__device__ float  g_v[M_QKV * DIM];
__device__ float  g_ctx[M_QKV * DIM];
__device__ float  g_attn[(size_t)NHEADS * SEQ * SEQ];
__device__ __half g_logit[(size_t)NHEADS * SEQ * SEQ];
__device__ float  g_tmax[(size_t)NHEADS * SEQ * NTILES];
__device__ float  g_tsum[(size_t)NHEADS * SEQ * NTILES];
__device__ float  g_rmax[(size_t)NHEADS * SEQ];
__device__ float  g_rinv[(size_t)NHEADS * SEQ];

// -------------------- mma / async helpers --------------------
// Operands fed as RAW fp32 — HMMA.TF32 truncates low mantissa bits in HW.
__device__ __forceinline__ void mma_tf32(float (&d)[4], const float (&a)[4], const float (&b)[2]) {
    asm volatile(
        "mma.sync.aligned.m16n8k8.row.col.f32.tf32.tf32.f32 "
        "{%0,%1,%2,%3}, {%4,%5,%6,%7}, {%8,%9}, {%0,%1,%2,%3};\n"
        : "+f"(d[0]), "+f"(d[1]), "+f"(d[2]), "+f"(d[3])
        : "r"(__float_as_uint(a[0])), "r"(__float_as_uint(a[1])),
          "r"(__float_as_uint(a[2])), "r"(__float_as_uint(a[3])),
          "r"(__float_as_uint(b[0])), "r"(__float_as_uint(b[1])));
}

__device__ __forceinline__ void cp_async16(uint32_t smem_dst, const void* gmem_src) {
    asm volatile("cp.async.cg.shared.global [%0], [%1], 16;\n"
                 :: "r"(smem_dst), "l"(gmem_src));
}
__device__ __forceinline__ void cp_async_commit() {
    asm volatile("cp.async.commit_group;\n");
}
__device__ __forceinline__ void cp_async_wait_all() {
    asm volatile("cp.async.wait_group 0;\n");
}

__device__ __forceinline__ void softmax_comb(float& m, float& s, float m2, float s2) {
    float M = fmaxf(m, m2);
    s = s * __expf(m - M) + s2 * __expf(m2 - M);
    m = M;
}

// ============================================================================
// Kernel 1: QKV projections — BK=32, dynamic double-buffered smem + cp.async.
// ============================================================================
__global__ __launch_bounds__(256, 2)
void qkv_tc(const float* __restrict__ Xq, const float* __restrict__ Xk, const float* __restrict__ Xv,
            const float* __restrict__ Wq, const float* __restrict__ Wk, const float* __restrict__ Wv,
            const float* __restrict__ bq, const float* __restrict__ bk, const float* __restrict__ bv)
{
    extern __shared__ float qsm[];
    float* Abuf[2] = { qsm,                qsm + 128 * QSTR };
    float* Bbuf[2] = { qsm + 2*128*QSTR,   qsm + 3*128*QSTR };

    const int z = blockIdx.z;
    const float* A    = (z == 0) ? Xq : (z == 1) ? Xk : Xv;
    const float* W    = (z == 0) ? Wq : (z == 1) ? Wk : Wv;
    const float* bias = (z == 0) ? bq : (z == 1) ? bk : bv;
    float*       C    = (z == 0) ? g_q : (z == 1) ? g_k : g_v;

    const int tid  = threadIdx.x;
    const int lane = tid & 31;
    const int warp = tid >> 5;
    const int g    = lane >> 2;
    const int tg   = lane & 3;
    const int wm   = (warp >> 1) * 32;
    const int wn   = (warp & 1) * 64;
    const int m0   = blockIdx.y * 128;
    const int n0   = blockIdx.x * 128;

    // loader: 2 threads per row, 16 floats (4x cp.async16) each, per matrix
    const int lr = tid >> 1;             // 0..127
    const int lc = (tid & 1) * 16;       // 0 or 16

    const float* Ap = A + (size_t)(m0 + lr) * DIM + lc;
    const float* Wp = W + (size_t)(n0 + lr) * DIM + lc;

    uint32_t sA[2], sB[2];
    sA[0] = (uint32_t)__cvta_generic_to_shared(&Abuf[0][lr * QSTR + lc]);
    sA[1] = (uint32_t)__cvta_generic_to_shared(&Abuf[1][lr * QSTR + lc]);
    sB[0] = (uint32_t)__cvta_generic_to_shared(&Bbuf[0][lr * QSTR + lc]);
    sB[1] = (uint32_t)__cvta_generic_to_shared(&Bbuf[1][lr * QSTR + lc]);

    float acc[2][8][4];
#pragma unroll
    for (int i = 0; i < 2; i++)
#pragma unroll
        for (int j = 0; j < 8; j++)
#pragma unroll
            for (int q = 0; q < 4; q++) acc[i][j][q] = 0.f;

    // prologue: slab 0 -> buffer 0
#pragma unroll
    for (int c = 0; c < 4; c++) {
        cp_async16(sA[0] + c * 16, Ap + c * 4);
        cp_async16(sB[0] + c * 16, Wp + c * 4);
    }
    cp_async_commit();

    const int NIT = DIM / 32;   // 32
    for (int it = 0; it < NIT; it++) {
        cp_async_wait_all();
        __syncthreads();

        if (it + 1 < NIT) {
            const int k1 = (it + 1) * 32;
            const int nb = (it + 1) & 1;
#pragma unroll
            for (int c = 0; c < 4; c++) {
                cp_async16(sA[nb] + c * 16, Ap + k1 + c * 4);
                cp_async16(sB[nb] + c * 16, Wp + k1 + c * 4);
            }
            cp_async_commit();
        }

        const float* as = Abuf[it & 1];
        const float* bs = Bbuf[it & 1];
#pragma unroll
        for (int ks = 0; ks < 4; ks++) {
            const int kb = ks * 8;
            float af[2][4];
#pragma unroll
            for (int mt = 0; mt < 2; mt++) {
                const int rb = wm + mt * 16;
                af[mt][0] = as[(rb + g) * QSTR + kb + tg];
                af[mt][1] = as[(rb + g + 8) * QSTR + kb + tg];
                af[mt][2] = as[(rb + g) * QSTR + kb + tg + 4];
                af[mt][3] = as[(rb + g + 8) * QSTR + kb + tg + 4];
            }
            float bf[8][2];
#pragma unroll
            for (int nt = 0; nt < 8; nt++) {
                const int cb = wn + nt * 8;
                bf[nt][0] = bs[(cb + g) * QSTR + kb + tg];
                bf[nt][1] = bs[(cb + g) * QSTR + kb + tg + 4];
            }
#pragma unroll
            for (int mt = 0; mt < 2; mt++)
#pragma unroll
                for (int nt = 0; nt < 8; nt++)
                    mma_tf32(acc[mt][nt], af[mt], bf[nt]);
        }
    }

#pragma unroll
    for (int mt = 0; mt < 2; mt++)
#pragma unroll
        for (int nt = 0; nt < 8; nt++) {
            const int row = m0 + wm + mt * 16 + g;
            const int col = n0 + wn + nt * 8 + 2 * tg;
            const float bx = bias[col], by = bias[col + 1];
            float2 o0 = make_float2(acc[mt][nt][0] + bx, acc[mt][nt][1] + by);
            float2 o1 = make_float2(acc[mt][nt][2] + bx, acc[mt][nt][3] + by);
            *(float2*)&C[(size_t)row * DIM + col]       = o0;
            *(float2*)&C[(size_t)(row + 8) * DIM + col] = o1;
        }
}

// ============================================================================
// Kernel 2: scores = scale*Q K^T -> fp16 logits (streaming) + per-tile stats.
// ============================================================================
__global__ __launch_bounds__(256, 2)
void scores_tc()
{
    __shared__ float As[128 * SSTR];
    __shared__ float Bs[128 * SSTR];
    __shared__ float sm_m[128][2];
    __shared__ float sm_s[128][2];

    const int bh = blockIdx.z;
    const float* Q = g_q + (size_t)bh * SEQ * HDIM;
    const float* K = g_k + (size_t)bh * SEQ * HDIM;
    __half*      L = g_logit + (size_t)bh * SEQ * SEQ;

    const int tid  = threadIdx.x;
    const int lane = tid & 31;
    const int warp = tid >> 5;
    const int g    = lane >> 2;
    const int tg   = lane & 3;
    const int wm   = (warp >> 1) * 32;
    const int wn   = (warp & 1) * 64;
    const int wn_half = warp & 1;
    const int m0   = blockIdx.y * 128;
    const int n0   = blockIdx.x * 128;
    const int lr   = tid >> 2;
    const int lc   = (tid & 3) * 4;

    const float* Qp  = Q + (size_t)(m0 + lr) * HDIM + lc;
    const float* Qp2 = Q + (size_t)(m0 + lr + 64) * HDIM + lc;
    const float* Kp  = K + (size_t)(n0 + lr) * HDIM + lc;
    const float* Kp2 = K + (size_t)(n0 + lr + 64) * HDIM + lc;

    float acc[2][8][4];
#pragma unroll
    for (int i = 0; i < 2; i++)
#pragma unroll
        for (int j = 0; j < 8; j++)
#pragma unroll
            for (int q = 0; q < 4; q++) acc[i][j][q] = 0.f;

    float4 ra0 = *(const float4*)(Qp);
    float4 ra1 = *(const float4*)(Qp2);
    float4 rb0 = *(const float4*)(Kp);
    float4 rb1 = *(const float4*)(Kp2);

    for (int k0 = 0; k0 < HDIM; k0 += 16) {
        *(float4*)&As[lr * SSTR + lc]        = ra0;
        *(float4*)&As[(lr + 64) * SSTR + lc] = ra1;
        *(float4*)&Bs[lr * SSTR + lc]        = rb0;
        *(float4*)&Bs[(lr + 64) * SSTR + lc] = rb1;
        __syncthreads();

        if (k0 + 16 < HDIM) {
            ra0 = *(const float4*)(Qp  + k0 + 16);
            ra1 = *(const float4*)(Qp2 + k0 + 16);
            rb0 = *(const float4*)(Kp  + k0 + 16);
            rb1 = *(const float4*)(Kp2 + k0 + 16);
        }

#pragma unroll
        for (int ks = 0; ks < 2; ks++) {
            const int kb = ks * 8;
            float af[2][4];
#pragma unroll
            for (int mt = 0; mt < 2; mt++) {
                const int rb = wm + mt * 16;
                af[mt][0] = As[(rb + g) * SSTR + kb + tg];
                af[mt][1] = As[(rb + g + 8) * SSTR + kb + tg];
                af[mt][2] = As[(rb + g) * SSTR + kb + tg + 4];
                af[mt][3] = As[(rb + g + 8) * SSTR + kb + tg + 4];
            }
            float bf[8][2];
#pragma unroll
            for (int nt = 0; nt < 8; nt++) {
                const int cb = wn + nt * 8;
                bf[nt][0] = Bs[(cb + g) * SSTR + kb + tg];
                bf[nt][1] = Bs[(cb + g) * SSTR + kb + tg + 4];
            }
#pragma unroll
            for (int mt = 0; mt < 2; mt++)
#pragma unroll
                for (int nt = 0; nt < 8; nt++)
                    mma_tf32(acc[mt][nt], af[mt], bf[nt]);
        }
        __syncthreads();
    }

#pragma unroll
    for (int mt = 0; mt < 2; mt++)
#pragma unroll
        for (int nt = 0; nt < 8; nt++)
#pragma unroll
            for (int q = 0; q < 4; q++) acc[mt][nt][q] *= SCALE;

    // write fp16 logits — streaming stores (never re-read by this kernel)
#pragma unroll
    for (int mt = 0; mt < 2; mt++)
#pragma unroll
        for (int nt = 0; nt < 8; nt++) {
            const int row = m0 + wm + mt * 16 + g;
            const int col = n0 + wn + nt * 8 + 2 * tg;
            __half2 h0 = __floats2half2_rn(acc[mt][nt][0], acc[mt][nt][1]);
            __half2 h1 = __floats2half2_rn(acc[mt][nt][2], acc[mt][nt][3]);
            __stcs((unsigned int*)&L[(size_t)row * SEQ + col],       *(unsigned int*)&h0);
            __stcs((unsigned int*)&L[(size_t)(row + 8) * SEQ + col], *(unsigned int*)&h1);
        }

    // per-tile softmax stats
#pragma unroll
    for (int mt = 0; mt < 2; mt++) {
#pragma unroll
        for (int h = 0; h < 2; h++) {
            const int q0 = h * 2;
            float m = -3.4e38f;
#pragma unroll
            for (int nt = 0; nt < 8; nt++)
                m = fmaxf(m, fmaxf(acc[mt][nt][q0], acc[mt][nt][q0 + 1]));
            float s = 0.f;
#pragma unroll
            for (int nt = 0; nt < 8; nt++)
                s += __expf(acc[mt][nt][q0] - m) + __expf(acc[mt][nt][q0 + 1] - m);
#pragma unroll
            for (int off = 1; off <= 2; off <<= 1) {
                float mo = __shfl_xor_sync(0xffffffffu, m, off);
                float so = __shfl_xor_sync(0xffffffffu, s, off);
                softmax_comb(m, s, mo, so);
            }
            if (tg == 0) {
                const int r = wm + mt * 16 + h * 8 + g;
                sm_m[r][wn_half] = m;
                sm_s[r][wn_half] = s;
            }
        }
    }
    __syncthreads();

    if (tid < 128) {
        float m = sm_m[tid][0], s = sm_s[tid][0];
        softmax_comb(m, s, sm_m[tid][1], sm_s[tid][1]);
        const size_t idx = ((size_t)bh * SEQ + m0 + tid) * NTILES + blockIdx.x;
        g_tmax[idx] = m;
        g_tsum[idx] = s;
    }
}

// ============================================================================
// Kernel 2b: fold per-tile stats into per-row (max, 1/sum).
// ============================================================================
__global__ __launch_bounds__(256)
void rowstats_kernel()
{
    const int row = blockIdx.x * 256 + threadIdx.x;
    const float* tm = &g_tmax[(size_t)row * NTILES];
    const float* ts = &g_tsum[(size_t)row * NTILES];
    float m = tm[0], s = ts[0];
#pragma unroll
    for (int t = 1; t < NTILES; t++)
        softmax_comb(m, s, tm[t], ts[t]);
    g_rmax[row] = m;
    g_rinv[row] = 1.0f / s;
}

// ============================================================================
// Kernel 3: pv — BK=32.  Each thread stages 16 halfs = TWO uint4 loads
// (the R10 bug: one uint4 is only 8 halfs; decoding 16 read OOB -> NaN).
// Normalizes, writes fp32 P (streaming, graded), ctx = P @ V via tf32 MMA.
// ============================================================================
__global__ __launch_bounds__(256, 2)
void pv_tc(float* attn_ext)
{
    float* attn = attn_ext ? attn_ext : g_attn;

    __shared__ float Ps[128 * QSTR];   // 128 x 32, stride 36
    __shared__ float Vs[32 * VSTR];    // 32 x 64,  stride 72

    const int bh = blockIdx.z;
    float*        P  = attn    + (size_t)bh * SEQ * SEQ;
    const __half* Lh = g_logit + (size_t)bh * SEQ * SEQ;
    const float*  V  = g_v     + (size_t)bh * SEQ * HDIM;
    float*        C  = g_ctx   + (size_t)bh * SEQ * HDIM;

    const int tid  = threadIdx.x;
    const int lane = tid & 31;
    const int warp = tid >> 5;
    const int g    = lane >> 2;
    const int tg   = lane & 3;
    const int wm   = (warp >> 1) * 32;
    const int wn   = (warp & 1) * 32;
    const int m0   = blockIdx.y * 128;

    // P loader: 2 threads per row, 16 halfs (= 2 x uint4) each
    const int prow = tid >> 1;            // 0..127
    const int pcol = (tid & 1) * 16;      // 0 or 16
    // V loader: rows vr and vr+16, 4 floats each
    const int vr   = tid >> 4;            // 0..15
    const int vc   = (tid & 15) * 4;      // 0..60

    const __half* Lp = Lh + (size_t)(m0 + prow) * SEQ + pcol;
    float*        Pp = P  + (size_t)(m0 + prow) * SEQ + pcol;
    const float*  Vp = V + (size_t)vr * HDIM + vc;

    const size_t rbase = (size_t)bh * SEQ + m0;
    const float rm = g_rmax[rbase + prow];
    const float ri = g_rinv[rbase + prow];

    float acc[2][4][4];
#pragma unroll
    for (int i = 0; i < 2; i++)
#pragma unroll
        for (int j = 0; j < 4; j++)
#pragma unroll
            for (int q = 0; q < 4; q++) acc[i][j][q] = 0.f;

    uint4  rla = __ldcs((const uint4*)(Lp));        // halfs 0..7
    uint4  rlb = __ldcs((const uint4*)(Lp + 8));    // halfs 8..15
    float4 rv0 = *(const float4*)(Vp);
    float4 rv1 = *(const float4*)(Vp + 16 * HDIM);

    for (int k0 = 0; k0 < SEQ; k0 += 32) {
        // decode 16 fp16 logits (32 bytes) -> normalize -> fp32 P + smem
        const uint32_t w[8] = { rla.x, rla.y, rla.z, rla.w,
                                rlb.x, rlb.y, rlb.z, rlb.w };
        float p[16];
#pragma unroll
        for (int i = 0; i < 8; i++) {
            float2 f = __half22float2(*(const __half2*)&w[i]);
            p[i * 2 + 0] = __expf(f.x - rm) * ri;
            p[i * 2 + 1] = __expf(f.y - rm) * ri;
        }

#pragma unroll
        for (int c = 0; c < 4; c++) {
            float4 o = make_float4(p[c * 4], p[c * 4 + 1], p[c * 4 + 2], p[c * 4 + 3]);
            __stcs((float4*)(Pp + k0 + c * 4), o);
            *(float4*)&Ps[prow * QSTR + pcol + c * 4] = o;
        }
        *(float4*)&Vs[vr * VSTR + vc]        = rv0;
        *(float4*)&Vs[(vr + 16) * VSTR + vc] = rv1;
        __syncthreads();

        if (k0 + 32 < SEQ) {
            rla = __ldcs((const uint4*)(Lp + k0 + 32));
            rlb = __ldcs((const uint4*)(Lp + k0 + 40));
            rv0 = *(const float4*)(Vp + (size_t)(k0 + 32) * HDIM);
            rv1 = *(const float4*)(Vp + (size_t)(k0 + 48) * HDIM);
        }

#pragma unroll
        for (int ks = 0; ks < 4; ks++) {
            const int kb = ks * 8;
            float af[2][4];
#pragma unroll
            for (int mt = 0; mt < 2; mt++) {
                const int rb = wm + mt * 16;
                af[mt][0] = Ps[(rb + g) * QSTR + kb + tg];
                af[mt][1] = Ps[(rb + g + 8) * QSTR + kb + tg];
                af[mt][2] = Ps[(rb + g) * QSTR + kb + tg + 4];
                af[mt][3] = Ps[(rb + g + 8) * QSTR + kb + tg + 4];
            }
            float bf[4][2];
#pragma unroll
            for (int nt = 0; nt < 4; nt++) {
                const int cb = wn + nt * 8;
                bf[nt][0] = Vs[(kb + tg) * VSTR + cb + g];
                bf[nt][1] = Vs[(kb + tg + 4) * VSTR + cb + g];
            }
#pragma unroll
            for (int mt = 0; mt < 2; mt++)
#pragma unroll
                for (int nt = 0; nt < 4; nt++)
                    mma_tf32(acc[mt][nt], af[mt], bf[nt]);
        }
        __syncthreads();
    }

#pragma unroll
    for (int mt = 0; mt < 2; mt++)
#pragma unroll
        for (int nt = 0; nt < 4; nt++) {
            const int row = m0 + wm + mt * 16 + g;
            const int col = wn + nt * 8 + 2 * tg;
            *(float2*)&C[(size_t)row * HDIM + col]       = make_float2(acc[mt][nt][0], acc[mt][nt][1]);
            *(float2*)&C[(size_t)(row + 8) * HDIM + col] = make_float2(acc[mt][nt][2], acc[mt][nt][3]);
        }
}

// ============================================================================
// Kernel 4: output = LayerNorm(query + context) * gamma + beta (unchanged).
// ============================================================================
__global__ __launch_bounds__(256)
void ln_kernel(const float* __restrict__ query, const float* __restrict__ gamma,
               const float* __restrict__ beta, float* __restrict__ out)
{
    const int row = blockIdx.x;
    const int t   = threadIdx.x;
    const float* qp = query + (size_t)row * DIM;
    const float* cp = g_ctx + (size_t)row * DIM;

    float4 qv = *(const float4*)&qp[t * 4];
    float4 cv = *(const float4*)&cp[t * 4];
    float x0 = qv.x + cv.x, x1 = qv.y + cv.y, x2 = qv.z + cv.z, x3 = qv.w + cv.w;

    __shared__ float red[256];
    red[t] = x0 + x1 + x2 + x3;
    __syncthreads();
#pragma unroll
    for (int s = 128; s > 0; s >>= 1) {
        if (t < s) red[t] += red[t + s];
        __syncthreads();
    }
    const float mu = red[0] * (1.0f / (float)DIM);
    __syncthreads();

    float d0 = x0 - mu, d1 = x1 - mu, d2 = x2 - mu, d3 = x3 - mu;
    red[t] = d0 * d0 + d1 * d1 + d2 * d2 + d3 * d3;
    __syncthreads();
#pragma unroll
    for (int s = 128; s > 0; s >>= 1) {
        if (t < s) red[t] += red[t + s];
        __syncthreads();
    }
    const float rs = rsqrtf(red[0] * (1.0f / (float)DIM) + LN_EPS);

    float4 g4 = *(const float4*)&gamma[t * 4];
    float4 b4 = *(const float4*)&beta[t * 4];
    float4 o  = make_float4(d0 * rs * g4.x + b4.x,
                            d1 * rs * g4.y + b4.y,
                            d2 * rs * g4.z + b4.z,
                            d3 * rs * g4.w + b4.w);
    *(float4*)&out[(size_t)row * DIM + t * 4] = o;
}

// ============================================================================
// Launcher.
// ============================================================================
extern "C" void kernel_launch(void* const* d_in, const int* in_sizes, int n_in,
                              void* d_out, int out_size)
{
    (void)in_sizes; (void)n_in;
    const float* key   = (const float*)d_in[0];
    const float* value = (const float*)d_in[1];
    const float* query = (const float*)d_in[2];
    const float* Wq    = (const float*)d_in[3];
    const float* bq    = (const float*)d_in[4];
    const float* Wk    = (const float*)d_in[5];
    const float* bk    = (const float*)d_in[6];
    const float* Wv    = (const float*)d_in[7];
    const float* bv    = (const float*)d_in[8];
    const float* gamma = (const float*)d_in[9];
    const float* beta  = (const float*)d_in[10];

    float* out = (float*)d_out;
    const long long OUT_ELEMS  = (long long)M_QKV * DIM;
    const long long ATTN_ELEMS = (long long)NHEADS * SEQ * SEQ;
    float* attn_ext = ((long long)out_size >= OUT_ELEMS + ATTN_ELEMS)
                          ? (out + OUT_ELEMS) : nullptr;

    cudaFuncSetAttribute(qkv_tc, cudaFuncAttributeMaxDynamicSharedMemorySize,
                         QKV_SMEM_BYTES);

    dim3 g1(DIM / 128, M_QKV / 128, 3);          // (8, 32, 3)
    qkv_tc<<<g1, 256, QKV_SMEM_BYTES>>>(query, key, value, Wq, Wk, Wv, bq, bk, bv);

    dim3 g2(SEQ / 128, SEQ / 128, NHEADS);       // (8, 8, 64)
    scores_tc<<<g2, 256>>>();

    rowstats_kernel<<<NHEADS * SEQ / 256, 256>>>();

    dim3 g4(1, SEQ / 128, NHEADS);               // (1, 8, 64)
    pv_tc<<<g4, 256>>>(attn_ext);

    ln_kernel<<<M_QKV, 256>>>(query, gamma, beta, out);
}

// round 12
// speedup vs baseline: 1.1396x; 1.1396x over previous
#include <cuda_runtime.h>
#include <cuda_fp16.h>
#include <math.h>
#include <stdint.h>

// B=4, S=1024, D=1024, H=16, DH=64 -> BH=64 heads, per-head Q/K/V = [1024,64] contiguous
#define M_QKV   4096
#define DIM     1024
#define NHEADS  64
#define SEQ     1024
#define HDIM    64
#define SCALE   0.03125f      // D^-0.5
#define LN_EPS  1e-5f

#define SSTR    20            // smem row stride (floats): conflict-free frag loads
#define VSTR    72            // V tile stride
#define NTILES  8

#define QKV_STAGES 3
#define QKV_SMEM_FLOATS (QKV_STAGES * 2 * 128 * SSTR)   // 3 stages x 2 mats x 128 rows
#define QKV_SMEM_BYTES  (QKV_SMEM_FLOATS * 4)           // 61,440 B

// -------------------- scratch (allocation-free: __device__ globals) --------------------
__device__ float  g_q[M_QKV * DIM];
__device__ float  g_k[M_QKV * DIM];
__device__ float  g_v[M_QKV * DIM];
__device__ float  g_ctx[M_QKV * DIM];
__device__ float  g_attn[(size_t)NHEADS * SEQ * SEQ];
__device__ __half g_logit[(size_t)NHEADS * SEQ * SEQ];
__device__ float  g_tmax[(size_t)NHEADS * SEQ * NTILES];
__device__ float  g_tsum[(size_t)NHEADS * SEQ * NTILES];
__device__ float  g_rmax[(size_t)NHEADS * SEQ];
__device__ float  g_rinv[(size_t)NHEADS * SEQ];

// -------------------- mma / async helpers --------------------
// Operands fed as RAW fp32 — HMMA.TF32 truncates low mantissa bits in HW.
__device__ __forceinline__ void mma_tf32(float (&d)[4], const float (&a)[4], const float (&b)[2]) {
    asm volatile(
        "mma.sync.aligned.m16n8k8.row.col.f32.tf32.tf32.f32 "
        "{%0,%1,%2,%3}, {%4,%5,%6,%7}, {%8,%9}, {%0,%1,%2,%3};\n"
        : "+f"(d[0]), "+f"(d[1]), "+f"(d[2]), "+f"(d[3])
        : "r"(__float_as_uint(a[0])), "r"(__float_as_uint(a[1])),
          "r"(__float_as_uint(a[2])), "r"(__float_as_uint(a[3])),
          "r"(__float_as_uint(b[0])), "r"(__float_as_uint(b[1])));
}

__device__ __forceinline__ void cp_async16(uint32_t smem_dst, const void* gmem_src) {
    asm volatile("cp.async.cg.shared.global [%0], [%1], 16;\n"
                 :: "r"(smem_dst), "l"(gmem_src));
}
__device__ __forceinline__ void cp_async_commit() {
    asm volatile("cp.async.commit_group;\n");
}
template <int N>
__device__ __forceinline__ void cp_async_wait() {
    asm volatile("cp.async.wait_group %0;\n" :: "n"(N));
}

__device__ __forceinline__ void softmax_comb(float& m, float& s, float m2, float s2) {
    float M = fmaxf(m, m2);
    s = s * __expf(m - M) + s2 * __expf(m2 - M);
    m = M;
}

// ============================================================================
// Kernel 1: QKV projections — BK=16, THREE-stage cp.async pipeline.
// Loader pattern identical to R9 (warp = 8 rows x 64B contiguous).
// wait_group<1> keeps two slabs in flight during compute.
// ============================================================================
__global__ __launch_bounds__(256, 2)
void qkv_tc(const float* __restrict__ Xq, const float* __restrict__ Xk, const float* __restrict__ Xv,
            const float* __restrict__ Wq, const float* __restrict__ Wk, const float* __restrict__ Wv,
            const float* __restrict__ bq, const float* __restrict__ bk, const float* __restrict__ bv)
{
    extern __shared__ float qsm[];
    // layout: stage s -> A at qsm + s*2*128*SSTR, B at +128*SSTR
    const int z = blockIdx.z;
    const float* A    = (z == 0) ? Xq : (z == 1) ? Xk : Xv;
    const float* W    = (z == 0) ? Wq : (z == 1) ? Wk : Wv;
    const float* bias = (z == 0) ? bq : (z == 1) ? bk : bv;
    float*       C    = (z == 0) ? g_q : (z == 1) ? g_k : g_v;

    const int tid  = threadIdx.x;
    const int lane = tid & 31;
    const int warp = tid >> 5;
    const int g    = lane >> 2;
    const int tg   = lane & 3;
    const int wm   = (warp >> 1) * 32;
    const int wn   = (warp & 1) * 64;
    const int m0   = blockIdx.y * 128;
    const int n0   = blockIdx.x * 128;
    const int lr   = tid >> 2;        // 0..63
    const int lc   = (tid & 3) * 4;   // 0,4,8,12

    const float* Ap  = A + (size_t)(m0 + lr) * DIM + lc;
    const float* Ap2 = A + (size_t)(m0 + lr + 64) * DIM + lc;
    const float* Wp  = W + (size_t)(n0 + lr) * DIM + lc;
    const float* Wp2 = W + (size_t)(n0 + lr + 64) * DIM + lc;

    uint32_t sA[QKV_STAGES], sB[QKV_STAGES];
#pragma unroll
    for (int s = 0; s < QKV_STAGES; s++) {
        sA[s] = (uint32_t)__cvta_generic_to_shared(qsm + s * 2 * 128 * SSTR + lr * SSTR + lc);
        sB[s] = (uint32_t)__cvta_generic_to_shared(qsm + (s * 2 + 1) * 128 * SSTR + lr * SSTR + lc);
    }
    const uint32_t rowoff = 64 * SSTR * 4;   // +64 rows, bytes

    float acc[2][8][4];
#pragma unroll
    for (int i = 0; i < 2; i++)
#pragma unroll
        for (int j = 0; j < 8; j++)
#pragma unroll
            for (int q = 0; q < 4; q++) acc[i][j][q] = 0.f;

    // prologue: slabs 0 and 1 in flight
#pragma unroll
    for (int s = 0; s < 2; s++) {
        const int k = s * 16;
        cp_async16(sA[s],          Ap  + k);
        cp_async16(sA[s] + rowoff, Ap2 + k);
        cp_async16(sB[s],          Wp  + k);
        cp_async16(sB[s] + rowoff, Wp2 + k);
        cp_async_commit();
    }

    const int NIT = DIM / 16;   // 64
    for (int it = 0; it < NIT; it++) {
        cp_async_wait<1>();       // slab `it` resident; slab it+1 may still fly
        __syncthreads();

        if (it + 2 < NIT) {
            const int k2 = (it + 2) * 16;
            const int nb = (it + 2) % QKV_STAGES;
            cp_async16(sA[nb],          Ap  + k2);
            cp_async16(sA[nb] + rowoff, Ap2 + k2);
            cp_async16(sB[nb],          Wp  + k2);
            cp_async16(sB[nb] + rowoff, Wp2 + k2);
            cp_async_commit();
        }

        const int cb_ = it % QKV_STAGES;
        const float* as = qsm + cb_ * 2 * 128 * SSTR;
        const float* bs = as + 128 * SSTR;
#pragma unroll
        for (int ks = 0; ks < 2; ks++) {
            const int kb = ks * 8;
            float af[2][4];
#pragma unroll
            for (int mt = 0; mt < 2; mt++) {
                const int rb = wm + mt * 16;
                af[mt][0] = as[(rb + g) * SSTR + kb + tg];
                af[mt][1] = as[(rb + g + 8) * SSTR + kb + tg];
                af[mt][2] = as[(rb + g) * SSTR + kb + tg + 4];
                af[mt][3] = as[(rb + g + 8) * SSTR + kb + tg + 4];
            }
            float bf[8][2];
#pragma unroll
            for (int nt = 0; nt < 8; nt++) {
                const int cb = wn + nt * 8;
                bf[nt][0] = bs[(cb + g) * SSTR + kb + tg];
                bf[nt][1] = bs[(cb + g) * SSTR + kb + tg + 4];
            }
#pragma unroll
            for (int mt = 0; mt < 2; mt++)
#pragma unroll
                for (int nt = 0; nt < 8; nt++)
                    mma_tf32(acc[mt][nt], af[mt], bf[nt]);
        }
    }

#pragma unroll
    for (int mt = 0; mt < 2; mt++)
#pragma unroll
        for (int nt = 0; nt < 8; nt++) {
            const int row = m0 + wm + mt * 16 + g;
            const int col = n0 + wn + nt * 8 + 2 * tg;
            const float bx = bias[col], by = bias[col + 1];
            float2 o0 = make_float2(acc[mt][nt][0] + bx, acc[mt][nt][1] + by);
            float2 o1 = make_float2(acc[mt][nt][2] + bx, acc[mt][nt][3] + by);
            *(float2*)&C[(size_t)row * DIM + col]       = o0;
            *(float2*)&C[(size_t)(row + 8) * DIM + col] = o1;
        }
}

// ============================================================================
// Kernel 2: scores = scale*Q K^T -> fp16 logits + per-tile stats (R9 verbatim).
// ============================================================================
__global__ __launch_bounds__(256, 2)
void scores_tc()
{
    __shared__ float As[128 * SSTR];
    __shared__ float Bs[128 * SSTR];
    __shared__ float sm_m[128][2];
    __shared__ float sm_s[128][2];

    const int bh = blockIdx.z;
    const float* Q = g_q + (size_t)bh * SEQ * HDIM;
    const float* K = g_k + (size_t)bh * SEQ * HDIM;
    __half*      L = g_logit + (size_t)bh * SEQ * SEQ;

    const int tid  = threadIdx.x;
    const int lane = tid & 31;
    const int warp = tid >> 5;
    const int g    = lane >> 2;
    const int tg   = lane & 3;
    const int wm   = (warp >> 1) * 32;
    const int wn   = (warp & 1) * 64;
    const int wn_half = warp & 1;
    const int m0   = blockIdx.y * 128;
    const int n0   = blockIdx.x * 128;
    const int lr   = tid >> 2;
    const int lc   = (tid & 3) * 4;

    const float* Qp  = Q + (size_t)(m0 + lr) * HDIM + lc;
    const float* Qp2 = Q + (size_t)(m0 + lr + 64) * HDIM + lc;
    const float* Kp  = K + (size_t)(n0 + lr) * HDIM + lc;
    const float* Kp2 = K + (size_t)(n0 + lr + 64) * HDIM + lc;

    float acc[2][8][4];
#pragma unroll
    for (int i = 0; i < 2; i++)
#pragma unroll
        for (int j = 0; j < 8; j++)
#pragma unroll
            for (int q = 0; q < 4; q++) acc[i][j][q] = 0.f;

    float4 ra0 = *(const float4*)(Qp);
    float4 ra1 = *(const float4*)(Qp2);
    float4 rb0 = *(const float4*)(Kp);
    float4 rb1 = *(const float4*)(Kp2);

    for (int k0 = 0; k0 < HDIM; k0 += 16) {
        *(float4*)&As[lr * SSTR + lc]        = ra0;
        *(float4*)&As[(lr + 64) * SSTR + lc] = ra1;
        *(float4*)&Bs[lr * SSTR + lc]        = rb0;
        *(float4*)&Bs[(lr + 64) * SSTR + lc] = rb1;
        __syncthreads();

        if (k0 + 16 < HDIM) {
            ra0 = *(const float4*)(Qp  + k0 + 16);
            ra1 = *(const float4*)(Qp2 + k0 + 16);
            rb0 = *(const float4*)(Kp  + k0 + 16);
            rb1 = *(const float4*)(Kp2 + k0 + 16);
        }

#pragma unroll
        for (int ks = 0; ks < 2; ks++) {
            const int kb = ks * 8;
            float af[2][4];
#pragma unroll
            for (int mt = 0; mt < 2; mt++) {
                const int rb = wm + mt * 16;
                af[mt][0] = As[(rb + g) * SSTR + kb + tg];
                af[mt][1] = As[(rb + g + 8) * SSTR + kb + tg];
                af[mt][2] = As[(rb + g) * SSTR + kb + tg + 4];
                af[mt][3] = As[(rb + g + 8) * SSTR + kb + tg + 4];
            }
            float bf[8][2];
#pragma unroll
            for (int nt = 0; nt < 8; nt++) {
                const int cb = wn + nt * 8;
                bf[nt][0] = Bs[(cb + g) * SSTR + kb + tg];
                bf[nt][1] = Bs[(cb + g) * SSTR + kb + tg + 4];
            }
#pragma unroll
            for (int mt = 0; mt < 2; mt++)
#pragma unroll
                for (int nt = 0; nt < 8; nt++)
                    mma_tf32(acc[mt][nt], af[mt], bf[nt]);
        }
        __syncthreads();
    }

#pragma unroll
    for (int mt = 0; mt < 2; mt++)
#pragma unroll
        for (int nt = 0; nt < 8; nt++)
#pragma unroll
            for (int q = 0; q < 4; q++) acc[mt][nt][q] *= SCALE;

#pragma unroll
    for (int mt = 0; mt < 2; mt++)
#pragma unroll
        for (int nt = 0; nt < 8; nt++) {
            const int row = m0 + wm + mt * 16 + g;
            const int col = n0 + wn + nt * 8 + 2 * tg;
            *(__half2*)&L[(size_t)row * SEQ + col]       = __floats2half2_rn(acc[mt][nt][0], acc[mt][nt][1]);
            *(__half2*)&L[(size_t)(row + 8) * SEQ + col] = __floats2half2_rn(acc[mt][nt][2], acc[mt][nt][3]);
        }

#pragma unroll
    for (int mt = 0; mt < 2; mt++) {
#pragma unroll
        for (int h = 0; h < 2; h++) {
            const int q0 = h * 2;
            float m = -3.4e38f;
#pragma unroll
            for (int nt = 0; nt < 8; nt++)
                m = fmaxf(m, fmaxf(acc[mt][nt][q0], acc[mt][nt][q0 + 1]));
            float s = 0.f;
#pragma unroll
            for (int nt = 0; nt < 8; nt++)
                s += __expf(acc[mt][nt][q0] - m) + __expf(acc[mt][nt][q0 + 1] - m);
#pragma unroll
            for (int off = 1; off <= 2; off <<= 1) {
                float mo = __shfl_xor_sync(0xffffffffu, m, off);
                float so = __shfl_xor_sync(0xffffffffu, s, off);
                softmax_comb(m, s, mo, so);
            }
            if (tg == 0) {
                const int r = wm + mt * 16 + h * 8 + g;
                sm_m[r][wn_half] = m;
                sm_s[r][wn_half] = s;
            }
        }
    }
    __syncthreads();

    if (tid < 128) {
        float m = sm_m[tid][0], s = sm_s[tid][0];
        softmax_comb(m, s, sm_m[tid][1], sm_s[tid][1]);
        const size_t idx = ((size_t)bh * SEQ + m0 + tid) * NTILES + blockIdx.x;
        g_tmax[idx] = m;
        g_tsum[idx] = s;
    }
}

// ============================================================================
// Kernel 2b: fold per-tile stats into per-row (max, 1/sum).
// ============================================================================
__global__ __launch_bounds__(256)
void rowstats_kernel()
{
    const int row = blockIdx.x * 256 + threadIdx.x;
    const float* tm = &g_tmax[(size_t)row * NTILES];
    const float* ts = &g_tsum[(size_t)row * NTILES];
    float m = tm[0], s = ts[0];
#pragma unroll
    for (int t = 1; t < NTILES; t++)
        softmax_comb(m, s, tm[t], ts[t]);
    g_rmax[row] = m;
    g_rinv[row] = 1.0f / s;
}

// ============================================================================
// Kernel 3: pv — R9 verbatim (BK=16).  fp16 logit read, normalize, fp32 P
// write (graded), ctx = P @ V via tf32 MMA.
// ============================================================================
__global__ __launch_bounds__(256, 2)
void pv_tc(float* attn_ext)
{
    float* attn = attn_ext ? attn_ext : g_attn;

    __shared__ float Ps[128 * SSTR];
    __shared__ float Vs[16 * VSTR];

    const int bh = blockIdx.z;
    float*        P  = attn    + (size_t)bh * SEQ * SEQ;
    const __half* Lh = g_logit + (size_t)bh * SEQ * SEQ;
    const float*  V  = g_v     + (size_t)bh * SEQ * HDIM;
    float*        C  = g_ctx   + (size_t)bh * SEQ * HDIM;

    const int tid  = threadIdx.x;
    const int lane = tid & 31;
    const int warp = tid >> 5;
    const int g    = lane >> 2;
    const int tg   = lane & 3;
    const int wm   = (warp >> 1) * 32;
    const int wn   = (warp & 1) * 32;
    const int m0   = blockIdx.y * 128;
    const int lr   = tid >> 2;
    const int lc   = (tid & 3) * 4;
    const int vr   = tid >> 4;
    const int vc   = (tid & 15) * 4;

    const __half* Lp  = Lh + (size_t)(m0 + lr) * SEQ + lc;
    const __half* Lp2 = Lh + (size_t)(m0 + lr + 64) * SEQ + lc;
    float* Pp  = P + (size_t)(m0 + lr) * SEQ + lc;
    float* Pp2 = P + (size_t)(m0 + lr + 64) * SEQ + lc;
    const float* Vp = V + (size_t)vr * HDIM + vc;

    const size_t rbase = (size_t)bh * SEQ + m0;
    const float rm0 = g_rmax[rbase + lr],      ri0 = g_rinv[rbase + lr];
    const float rm1 = g_rmax[rbase + lr + 64], ri1 = g_rinv[rbase + lr + 64];

    float acc[2][4][4];
#pragma unroll
    for (int i = 0; i < 2; i++)
#pragma unroll
        for (int j = 0; j < 4; j++)
#pragma unroll
            for (int q = 0; q < 4; q++) acc[i][j][q] = 0.f;

    uint2 rl0 = __ldcs((const uint2*)(Lp));
    uint2 rl1 = __ldcs((const uint2*)(Lp2));
    float4 rv = *(const float4*)(Vp);

    for (int k0 = 0; k0 < SEQ; k0 += 16) {
        float2 a0 = __half22float2(*(__half2*)&rl0.x);
        float2 a1 = __half22float2(*(__half2*)&rl0.y);
        float2 b0 = __half22float2(*(__half2*)&rl1.x);
        float2 b1 = __half22float2(*(__half2*)&rl1.y);

        float4 p0, p1;
        p0.x = __expf(a0.x - rm0) * ri0; p0.y = __expf(a0.y - rm0) * ri0;
        p0.z = __expf(a1.x - rm0) * ri0; p0.w = __expf(a1.y - rm0) * ri0;
        p1.x = __expf(b0.x - rm1) * ri1; p1.y = __expf(b0.y - rm1) * ri1;
        p1.z = __expf(b1.x - rm1) * ri1; p1.w = __expf(b1.y - rm1) * ri1;

        __stcs((float4*)(Pp  + k0), p0);
        __stcs((float4*)(Pp2 + k0), p1);

        *(float4*)&Ps[lr * SSTR + lc]        = p0;
        *(float4*)&Ps[(lr + 64) * SSTR + lc] = p1;
        *(float4*)&Vs[vr * VSTR + vc]        = rv;
        __syncthreads();

        if (k0 + 16 < SEQ) {
            rl0 = __ldcs((const uint2*)(Lp  + k0 + 16));
            rl1 = __ldcs((const uint2*)(Lp2 + k0 + 16));
            rv  = *(const float4*)(Vp + (size_t)(k0 + 16) * HDIM);
        }

#pragma unroll
        for (int ks = 0; ks < 2; ks++) {
            const int kb = ks * 8;
            float af[2][4];
#pragma unroll
            for (int mt = 0; mt < 2; mt++) {
                const int rb = wm + mt * 16;
                af[mt][0] = Ps[(rb + g) * SSTR + kb + tg];
                af[mt][1] = Ps[(rb + g + 8) * SSTR + kb + tg];
                af[mt][2] = Ps[(rb + g) * SSTR + kb + tg + 4];
                af[mt][3] = Ps[(rb + g + 8) * SSTR + kb + tg + 4];
            }
            float bf[4][2];
#pragma unroll
            for (int nt = 0; nt < 4; nt++) {
                const int cb = wn + nt * 8;
                bf[nt][0] = Vs[(kb + tg) * VSTR + cb + g];
                bf[nt][1] = Vs[(kb + tg + 4) * VSTR + cb + g];
            }
#pragma unroll
            for (int mt = 0; mt < 2; mt++)
#pragma unroll
                for (int nt = 0; nt < 4; nt++)
                    mma_tf32(acc[mt][nt], af[mt], bf[nt]);
        }
        __syncthreads();
    }

#pragma unroll
    for (int mt = 0; mt < 2; mt++)
#pragma unroll
        for (int nt = 0; nt < 4; nt++) {
            const int row = m0 + wm + mt * 16 + g;
            const int col = wn + nt * 8 + 2 * tg;
            *(float2*)&C[(size_t)row * HDIM + col]       = make_float2(acc[mt][nt][0], acc[mt][nt][1]);
            *(float2*)&C[(size_t)(row + 8) * HDIM + col] = make_float2(acc[mt][nt][2], acc[mt][nt][3]);
        }
}

// ============================================================================
// Kernel 4: output = LayerNorm(query + context) * gamma + beta (unchanged).
// ============================================================================
__global__ __launch_bounds__(256)
void ln_kernel(const float* __restrict__ query, const float* __restrict__ gamma,
               const float* __restrict__ beta, float* __restrict__ out)
{
    const int row = blockIdx.x;
    const int t   = threadIdx.x;
    const float* qp = query + (size_t)row * DIM;
    const float* cp = g_ctx + (size_t)row * DIM;

    float4 qv = *(const float4*)&qp[t * 4];
    float4 cv = *(const float4*)&cp[t * 4];
    float x0 = qv.x + cv.x, x1 = qv.y + cv.y, x2 = qv.z + cv.z, x3 = qv.w + cv.w;

    __shared__ float red[256];
    red[t] = x0 + x1 + x2 + x3;
    __syncthreads();
#pragma unroll
    for (int s = 128; s > 0; s >>= 1) {
        if (t < s) red[t] += red[t + s];
        __syncthreads();
    }
    const float mu = red[0] * (1.0f / (float)DIM);
    __syncthreads();

    float d0 = x0 - mu, d1 = x1 - mu, d2 = x2 - mu, d3 = x3 - mu;
    red[t] = d0 * d0 + d1 * d1 + d2 * d2 + d3 * d3;
    __syncthreads();
#pragma unroll
    for (int s = 128; s > 0; s >>= 1) {
        if (t < s) red[t] += red[t + s];
        __syncthreads();
    }
    const float rs = rsqrtf(red[0] * (1.0f / (float)DIM) + LN_EPS);

    float4 g4 = *(const float4*)&gamma[t * 4];
    float4 b4 = *(const float4*)&beta[t * 4];
    float4 o  = make_float4(d0 * rs * g4.x + b4.x,
                            d1 * rs * g4.y + b4.y,
                            d2 * rs * g4.z + b4.z,
                            d3 * rs * g4.w + b4.w);
    *(float4*)&out[(size_t)row * DIM + t * 4] = o;
}

// ============================================================================
// Launcher.
// ============================================================================
extern "C" void kernel_launch(void* const* d_in, const int* in_sizes, int n_in,
                              void* d_out, int out_size)
{
    (void)in_sizes; (void)n_in;
    const float* key   = (const float*)d_in[0];
    const float* value = (const float*)d_in[1];
    const float* query = (const float*)d_in[2];
    const float* Wq    = (const float*)d_in[3];
    const float* bq    = (const float*)d_in[4];
    const float* Wk    = (const float*)d_in[5];
    const float* bk    = (const float*)d_in[6];
    const float* Wv    = (const float*)d_in[7];
    const float* bv    = (const float*)d_in[8];
    const float* gamma = (const float*)d_in[9];
    const float* beta  = (const float*)d_in[10];

    float* out = (float*)d_out;
    const long long OUT_ELEMS  = (long long)M_QKV * DIM;
    const long long ATTN_ELEMS = (long long)NHEADS * SEQ * SEQ;
    float* attn_ext = ((long long)out_size >= OUT_ELEMS + ATTN_ELEMS)
                          ? (out + OUT_ELEMS) : nullptr;

    cudaFuncSetAttribute(qkv_tc, cudaFuncAttributeMaxDynamicSharedMemorySize,
                         QKV_SMEM_BYTES);

    dim3 g1(DIM / 128, M_QKV / 128, 3);          // (8, 32, 3)
    qkv_tc<<<g1, 256, QKV_SMEM_BYTES>>>(query, key, value, Wq, Wk, Wv, bq, bk, bv);

    dim3 g2(SEQ / 128, SEQ / 128, NHEADS);       // (8, 8, 64)
    scores_tc<<<g2, 256>>>();

    rowstats_kernel<<<NHEADS * SEQ / 256, 256>>>();

    dim3 g4(1, SEQ / 128, NHEADS);               // (1, 8, 64)
    pv_tc<<<g4, 256>>>(attn_ext);

    ln_kernel<<<M_QKV, 256>>>(query, gamma, beta, out);
}

// round 13
// speedup vs baseline: 1.1451x; 1.0049x over previous
#include <cuda_runtime.h>
#include <cuda_fp16.h>
#include <math.h>
#include <stdint.h>

// B=4, S=1024, D=1024, H=16, DH=64 -> BH=64 heads, per-head Q/K/V = [1024,64] contiguous
#define M_QKV   4096
#define DIM     1024
#define NHEADS  64
#define SEQ     1024
#define HDIM    64
#define SCALE   0.03125f      // D^-0.5
#define LN_EPS  1e-5f

#define SSTR    20            // 16-wide tile stride (qkv/pv): conflict-free frags
#define FSTR    68            // 64-wide tile stride (scores full tile): 68%32==4
#define VSTR    72            // V tile stride: 72%32==8
#define NTILES  8

#define QKV_STAGES 3
#define QKV_SMEM_FLOATS (QKV_STAGES * 2 * 128 * SSTR)
#define QKV_SMEM_BYTES  (QKV_SMEM_FLOATS * 4)           // 61,440 B

// -------------------- scratch (allocation-free: __device__ globals) --------------------
__device__ float  g_q[M_QKV * DIM];
__device__ float  g_k[M_QKV * DIM];
__device__ float  g_v[M_QKV * DIM];
__device__ float  g_ctx[M_QKV * DIM];
__device__ float  g_attn[(size_t)NHEADS * SEQ * SEQ];
__device__ __half g_logit[(size_t)NHEADS * SEQ * SEQ];
__device__ float  g_tmax[(size_t)NHEADS * SEQ * NTILES];
__device__ float  g_tsum[(size_t)NHEADS * SEQ * NTILES];
__device__ float  g_rmax[(size_t)NHEADS * SEQ];
__device__ float  g_rinv[(size_t)NHEADS * SEQ];

// -------------------- mma / async helpers --------------------
// Operands fed as RAW fp32 — HMMA.TF32 truncates low mantissa bits in HW.
__device__ __forceinline__ void mma_tf32(float (&d)[4], const float (&a)[4], const float (&b)[2]) {
    asm volatile(
        "mma.sync.aligned.m16n8k8.row.col.f32.tf32.tf32.f32 "
        "{%0,%1,%2,%3}, {%4,%5,%6,%7}, {%8,%9}, {%0,%1,%2,%3};\n"
        : "+f"(d[0]), "+f"(d[1]), "+f"(d[2]), "+f"(d[3])
        : "r"(__float_as_uint(a[0])), "r"(__float_as_uint(a[1])),
          "r"(__float_as_uint(a[2])), "r"(__float_as_uint(a[3])),
          "r"(__float_as_uint(b[0])), "r"(__float_as_uint(b[1])));
}

__device__ __forceinline__ void cp_async16(uint32_t smem_dst, const void* gmem_src) {
    asm volatile("cp.async.cg.shared.global [%0], [%1], 16;\n"
                 :: "r"(smem_dst), "l"(gmem_src));
}
__device__ __forceinline__ void cp_async_commit() {
    asm volatile("cp.async.commit_group;\n");
}
template <int N>
__device__ __forceinline__ void cp_async_wait() {
    asm volatile("cp.async.wait_group %0;\n" :: "n"(N));
}

__device__ __forceinline__ void softmax_comb(float& m, float& s, float m2, float s2) {
    float M = fmaxf(m, m2);
    s = s * __expf(m - M) + s2 * __expf(m2 - M);
    m = M;
}

// ============================================================================
// Kernel 1: QKV projections — BK=16, 3-stage cp.async pipeline (R12 verbatim).
// ============================================================================
__global__ __launch_bounds__(256, 2)
void qkv_tc(const float* __restrict__ Xq, const float* __restrict__ Xk, const float* __restrict__ Xv,
            const float* __restrict__ Wq, const float* __restrict__ Wk, const float* __restrict__ Wv,
            const float* __restrict__ bq, const float* __restrict__ bk, const float* __restrict__ bv)
{
    extern __shared__ float qsm[];
    const int z = blockIdx.z;
    const float* A    = (z == 0) ? Xq : (z == 1) ? Xk : Xv;
    const float* W    = (z == 0) ? Wq : (z == 1) ? Wk : Wv;
    const float* bias = (z == 0) ? bq : (z == 1) ? bk : bv;
    float*       C    = (z == 0) ? g_q : (z == 1) ? g_k : g_v;

    const int tid  = threadIdx.x;
    const int lane = tid & 31;
    const int warp = tid >> 5;
    const int g    = lane >> 2;
    const int tg   = lane & 3;
    const int wm   = (warp >> 1) * 32;
    const int wn   = (warp & 1) * 64;
    const int m0   = blockIdx.y * 128;
    const int n0   = blockIdx.x * 128;
    const int lr   = tid >> 2;
    const int lc   = (tid & 3) * 4;

    const float* Ap  = A + (size_t)(m0 + lr) * DIM + lc;
    const float* Ap2 = A + (size_t)(m0 + lr + 64) * DIM + lc;
    const float* Wp  = W + (size_t)(n0 + lr) * DIM + lc;
    const float* Wp2 = W + (size_t)(n0 + lr + 64) * DIM + lc;

    uint32_t sA[QKV_STAGES], sB[QKV_STAGES];
#pragma unroll
    for (int s = 0; s < QKV_STAGES; s++) {
        sA[s] = (uint32_t)__cvta_generic_to_shared(qsm + s * 2 * 128 * SSTR + lr * SSTR + lc);
        sB[s] = (uint32_t)__cvta_generic_to_shared(qsm + (s * 2 + 1) * 128 * SSTR + lr * SSTR + lc);
    }
    const uint32_t rowoff = 64 * SSTR * 4;

    float acc[2][8][4];
#pragma unroll
    for (int i = 0; i < 2; i++)
#pragma unroll
        for (int j = 0; j < 8; j++)
#pragma unroll
            for (int q = 0; q < 4; q++) acc[i][j][q] = 0.f;

#pragma unroll
    for (int s = 0; s < 2; s++) {
        const int k = s * 16;
        cp_async16(sA[s],          Ap  + k);
        cp_async16(sA[s] + rowoff, Ap2 + k);
        cp_async16(sB[s],          Wp  + k);
        cp_async16(sB[s] + rowoff, Wp2 + k);
        cp_async_commit();
    }

    const int NIT = DIM / 16;   // 64
    for (int it = 0; it < NIT; it++) {
        cp_async_wait<1>();
        __syncthreads();

        if (it + 2 < NIT) {
            const int k2 = (it + 2) * 16;
            const int nb = (it + 2) % QKV_STAGES;
            cp_async16(sA[nb],          Ap  + k2);
            cp_async16(sA[nb] + rowoff, Ap2 + k2);
            cp_async16(sB[nb],          Wp  + k2);
            cp_async16(sB[nb] + rowoff, Wp2 + k2);
            cp_async_commit();
        }

        const int cb_ = it % QKV_STAGES;
        const float* as = qsm + cb_ * 2 * 128 * SSTR;
        const float* bs = as + 128 * SSTR;
#pragma unroll
        for (int ks = 0; ks < 2; ks++) {
            const int kb = ks * 8;
            float af[2][4];
#pragma unroll
            for (int mt = 0; mt < 2; mt++) {
                const int rb = wm + mt * 16;
                af[mt][0] = as[(rb + g) * SSTR + kb + tg];
                af[mt][1] = as[(rb + g + 8) * SSTR + kb + tg];
                af[mt][2] = as[(rb + g) * SSTR + kb + tg + 4];
                af[mt][3] = as[(rb + g + 8) * SSTR + kb + tg + 4];
            }
            float bf[8][2];
#pragma unroll
            for (int nt = 0; nt < 8; nt++) {
                const int cb = wn + nt * 8;
                bf[nt][0] = bs[(cb + g) * SSTR + kb + tg];
                bf[nt][1] = bs[(cb + g) * SSTR + kb + tg + 4];
            }
#pragma unroll
            for (int mt = 0; mt < 2; mt++)
#pragma unroll
                for (int nt = 0; nt < 8; nt++)
                    mma_tf32(acc[mt][nt], af[mt], bf[nt]);
        }
    }

#pragma unroll
    for (int mt = 0; mt < 2; mt++)
#pragma unroll
        for (int nt = 0; nt < 8; nt++) {
            const int row = m0 + wm + mt * 16 + g;
            const int col = n0 + wn + nt * 8 + 2 * tg;
            const float bx = bias[col], by = bias[col + 1];
            float2 o0 = make_float2(acc[mt][nt][0] + bx, acc[mt][nt][1] + by);
            float2 o1 = make_float2(acc[mt][nt][2] + bx, acc[mt][nt][3] + by);
            *(float2*)&C[(size_t)row * DIM + col]       = o0;
            *(float2*)&C[(size_t)(row + 8) * DIM + col] = o1;
        }
}

// ============================================================================
// Kernel 2: scores — FULL 128x64 Q/K tiles loaded once; single barrier before
// all 8 k-steps.  Same math/order as R12; writes fp16 logits + tile stats.
// ============================================================================
__global__ __launch_bounds__(256, 2)
void scores_tc()
{
    __shared__ float As[128 * FSTR];   // 34,816 B
    __shared__ float Bs[128 * FSTR];
    __shared__ float sm_m[128][2];
    __shared__ float sm_s[128][2];

    const int bh = blockIdx.z;
    const float* Q = g_q + (size_t)bh * SEQ * HDIM;
    const float* K = g_k + (size_t)bh * SEQ * HDIM;
    __half*      L = g_logit + (size_t)bh * SEQ * SEQ;

    const int tid  = threadIdx.x;
    const int lane = tid & 31;
    const int warp = tid >> 5;
    const int g    = lane >> 2;
    const int tg   = lane & 3;
    const int wm   = (warp >> 1) * 32;
    const int wn   = (warp & 1) * 64;
    const int wn_half = warp & 1;
    const int m0   = blockIdx.y * 128;
    const int n0   = blockIdx.x * 128;
    const int lr   = tid >> 2;        // 0..63
    const int lc   = (tid & 3) * 4;   // 0,4,8,12

    // load full tiles: rows lr & lr+64, k-offsets 0/16/32/48 (8 float4 per mat)
    const float* Qp  = Q + (size_t)(m0 + lr) * HDIM + lc;
    const float* Qp2 = Q + (size_t)(m0 + lr + 64) * HDIM + lc;
    const float* Kp  = K + (size_t)(n0 + lr) * HDIM + lc;
    const float* Kp2 = K + (size_t)(n0 + lr + 64) * HDIM + lc;
#pragma unroll
    for (int ko = 0; ko < HDIM; ko += 16) {
        *(float4*)&As[lr * FSTR + ko + lc]        = *(const float4*)(Qp  + ko);
        *(float4*)&As[(lr + 64) * FSTR + ko + lc] = *(const float4*)(Qp2 + ko);
        *(float4*)&Bs[lr * FSTR + ko + lc]        = *(const float4*)(Kp  + ko);
        *(float4*)&Bs[(lr + 64) * FSTR + ko + lc] = *(const float4*)(Kp2 + ko);
    }
    __syncthreads();

    float acc[2][8][4];
#pragma unroll
    for (int i = 0; i < 2; i++)
#pragma unroll
        for (int j = 0; j < 8; j++)
#pragma unroll
            for (int q = 0; q < 4; q++) acc[i][j][q] = 0.f;

#pragma unroll
    for (int ks = 0; ks < 8; ks++) {
        const int kb = ks * 8;
        float af[2][4];
#pragma unroll
        for (int mt = 0; mt < 2; mt++) {
            const int rb = wm + mt * 16;
            af[mt][0] = As[(rb + g) * FSTR + kb + tg];
            af[mt][1] = As[(rb + g + 8) * FSTR + kb + tg];
            af[mt][2] = As[(rb + g) * FSTR + kb + tg + 4];
            af[mt][3] = As[(rb + g + 8) * FSTR + kb + tg + 4];
        }
        float bf[8][2];
#pragma unroll
        for (int nt = 0; nt < 8; nt++) {
            const int cb = wn + nt * 8;
            bf[nt][0] = Bs[(cb + g) * FSTR + kb + tg];
            bf[nt][1] = Bs[(cb + g) * FSTR + kb + tg + 4];
        }
#pragma unroll
        for (int mt = 0; mt < 2; mt++)
#pragma unroll
            for (int nt = 0; nt < 8; nt++)
                mma_tf32(acc[mt][nt], af[mt], bf[nt]);
    }

#pragma unroll
    for (int mt = 0; mt < 2; mt++)
#pragma unroll
        for (int nt = 0; nt < 8; nt++)
#pragma unroll
            for (int q = 0; q < 4; q++) acc[mt][nt][q] *= SCALE;

#pragma unroll
    for (int mt = 0; mt < 2; mt++)
#pragma unroll
        for (int nt = 0; nt < 8; nt++) {
            const int row = m0 + wm + mt * 16 + g;
            const int col = n0 + wn + nt * 8 + 2 * tg;
            *(__half2*)&L[(size_t)row * SEQ + col]       = __floats2half2_rn(acc[mt][nt][0], acc[mt][nt][1]);
            *(__half2*)&L[(size_t)(row + 8) * SEQ + col] = __floats2half2_rn(acc[mt][nt][2], acc[mt][nt][3]);
        }

    // per-tile softmax stats (unchanged)
#pragma unroll
    for (int mt = 0; mt < 2; mt++) {
#pragma unroll
        for (int h = 0; h < 2; h++) {
            const int q0 = h * 2;
            float m = -3.4e38f;
#pragma unroll
            for (int nt = 0; nt < 8; nt++)
                m = fmaxf(m, fmaxf(acc[mt][nt][q0], acc[mt][nt][q0 + 1]));
            float s = 0.f;
#pragma unroll
            for (int nt = 0; nt < 8; nt++)
                s += __expf(acc[mt][nt][q0] - m) + __expf(acc[mt][nt][q0 + 1] - m);
#pragma unroll
            for (int off = 1; off <= 2; off <<= 1) {
                float mo = __shfl_xor_sync(0xffffffffu, m, off);
                float so = __shfl_xor_sync(0xffffffffu, s, off);
                softmax_comb(m, s, mo, so);
            }
            if (tg == 0) {
                const int r = wm + mt * 16 + h * 8 + g;
                sm_m[r][wn_half] = m;
                sm_s[r][wn_half] = s;
            }
        }
    }
    __syncthreads();

    if (tid < 128) {
        float m = sm_m[tid][0], s = sm_s[tid][0];
        softmax_comb(m, s, sm_m[tid][1], sm_s[tid][1]);
        const size_t idx = ((size_t)bh * SEQ + m0 + tid) * NTILES + blockIdx.x;
        g_tmax[idx] = m;
        g_tsum[idx] = s;
    }
}

// ============================================================================
// Kernel 2b: fold per-tile stats into per-row (max, 1/sum).
// ============================================================================
__global__ __launch_bounds__(256)
void rowstats_kernel()
{
    const int row = blockIdx.x * 256 + threadIdx.x;
    const float* tm = &g_tmax[(size_t)row * NTILES];
    const float* ts = &g_tsum[(size_t)row * NTILES];
    float m = tm[0], s = ts[0];
#pragma unroll
    for (int t = 1; t < NTILES; t++)
        softmax_comb(m, s, tm[t], ts[t]);
    g_rmax[row] = m;
    g_rinv[row] = 1.0f / s;
}

// ============================================================================
// Kernel 3: pv — double-buffered SMEM, ONE sync per k-slab (was two).
// Stage slab it+1 into buf[(it+1)&1] while computing MMA from buf[it&1].
// Same math & accumulation order as R12.
// ============================================================================
__global__ __launch_bounds__(256, 2)
void pv_tc(float* attn_ext)
{
    float* attn = attn_ext ? attn_ext : g_attn;

    __shared__ float Ps[2][128 * SSTR];
    __shared__ float Vs[2][16 * VSTR];

    const int bh = blockIdx.z;
    float*        P  = attn    + (size_t)bh * SEQ * SEQ;
    const __half* Lh = g_logit + (size_t)bh * SEQ * SEQ;
    const float*  V  = g_v     + (size_t)bh * SEQ * HDIM;
    float*        C  = g_ctx   + (size_t)bh * SEQ * HDIM;

    const int tid  = threadIdx.x;
    const int lane = tid & 31;
    const int warp = tid >> 5;
    const int g    = lane >> 2;
    const int tg   = lane & 3;
    const int wm   = (warp >> 1) * 32;
    const int wn   = (warp & 1) * 32;
    const int m0   = blockIdx.y * 128;
    const int lr   = tid >> 2;
    const int lc   = (tid & 3) * 4;
    const int vr   = tid >> 4;
    const int vc   = (tid & 15) * 4;

    const __half* Lp  = Lh + (size_t)(m0 + lr) * SEQ + lc;
    const __half* Lp2 = Lh + (size_t)(m0 + lr + 64) * SEQ + lc;
    float* Pp  = P + (size_t)(m0 + lr) * SEQ + lc;
    float* Pp2 = P + (size_t)(m0 + lr + 64) * SEQ + lc;
    const float* Vp = V + (size_t)vr * HDIM + vc;

    const size_t rbase = (size_t)bh * SEQ + m0;
    const float rm0 = g_rmax[rbase + lr],      ri0 = g_rinv[rbase + lr];
    const float rm1 = g_rmax[rbase + lr + 64], ri1 = g_rinv[rbase + lr + 64];

    float acc[2][4][4];
#pragma unroll
    for (int i = 0; i < 2; i++)
#pragma unroll
        for (int j = 0; j < 4; j++)
#pragma unroll
            for (int q = 0; q < 4; q++) acc[i][j][q] = 0.f;

    // ---- prologue: stage slab 0 into buffer 0 ----
    {
        uint2 rl0 = __ldcs((const uint2*)(Lp));
        uint2 rl1 = __ldcs((const uint2*)(Lp2));
        float4 rv = *(const float4*)(Vp);

        float2 a0 = __half22float2(*(__half2*)&rl0.x);
        float2 a1 = __half22float2(*(__half2*)&rl0.y);
        float2 b0 = __half22float2(*(__half2*)&rl1.x);
        float2 b1 = __half22float2(*(__half2*)&rl1.y);
        float4 p0, p1;
        p0.x = __expf(a0.x - rm0) * ri0; p0.y = __expf(a0.y - rm0) * ri0;
        p0.z = __expf(a1.x - rm0) * ri0; p0.w = __expf(a1.y - rm0) * ri0;
        p1.x = __expf(b0.x - rm1) * ri1; p1.y = __expf(b0.y - rm1) * ri1;
        p1.z = __expf(b1.x - rm1) * ri1; p1.w = __expf(b1.y - rm1) * ri1;
        __stcs((float4*)(Pp), p0);
        __stcs((float4*)(Pp2), p1);
        *(float4*)&Ps[0][lr * SSTR + lc]        = p0;
        *(float4*)&Ps[0][(lr + 64) * SSTR + lc] = p1;
        *(float4*)&Vs[0][vr * VSTR + vc]        = rv;
    }
    __syncthreads();

    for (int it = 0; it < SEQ / 16; it++) {      // 64 slabs
        const int cur = it & 1;

        // stage slab it+1 into the other buffer (overlaps with MMA below)
        if (it + 1 < SEQ / 16) {
            const int k1 = (it + 1) * 16;
            uint2 rl0 = __ldcs((const uint2*)(Lp  + k1));
            uint2 rl1 = __ldcs((const uint2*)(Lp2 + k1));
            float4 rv = *(const float4*)(Vp + (size_t)k1 * HDIM);

            float2 a0 = __half22float2(*(__half2*)&rl0.x);
            float2 a1 = __half22float2(*(__half2*)&rl0.y);
            float2 b0 = __half22float2(*(__half2*)&rl1.x);
            float2 b1 = __half22float2(*(__half2*)&rl1.y);
            float4 p0, p1;
            p0.x = __expf(a0.x - rm0) * ri0; p0.y = __expf(a0.y - rm0) * ri0;
            p0.z = __expf(a1.x - rm0) * ri0; p0.w = __expf(a1.y - rm0) * ri0;
            p1.x = __expf(b0.x - rm1) * ri1; p1.y = __expf(b0.y - rm1) * ri1;
            p1.z = __expf(b1.x - rm1) * ri1; p1.w = __expf(b1.y - rm1) * ri1;
            __stcs((float4*)(Pp  + k1), p0);
            __stcs((float4*)(Pp2 + k1), p1);
            *(float4*)&Ps[cur ^ 1][lr * SSTR + lc]        = p0;
            *(float4*)&Ps[cur ^ 1][(lr + 64) * SSTR + lc] = p1;
            *(float4*)&Vs[cur ^ 1][vr * VSTR + vc]        = rv;
        }

        // MMA from current buffer
#pragma unroll
        for (int ks = 0; ks < 2; ks++) {
            const int kb = ks * 8;
            float af[2][4];
#pragma unroll
            for (int mt = 0; mt < 2; mt++) {
                const int rb = wm + mt * 16;
                af[mt][0] = Ps[cur][(rb + g) * SSTR + kb + tg];
                af[mt][1] = Ps[cur][(rb + g + 8) * SSTR + kb + tg];
                af[mt][2] = Ps[cur][(rb + g) * SSTR + kb + tg + 4];
                af[mt][3] = Ps[cur][(rb + g + 8) * SSTR + kb + tg + 4];
            }
            float bf[4][2];
#pragma unroll
            for (int nt = 0; nt < 4; nt++) {
                const int cb = wn + nt * 8;
                bf[nt][0] = Vs[cur][(kb + tg) * VSTR + cb + g];
                bf[nt][1] = Vs[cur][(kb + tg + 4) * VSTR + cb + g];
            }
#pragma unroll
            for (int mt = 0; mt < 2; mt++)
#pragma unroll
                for (int nt = 0; nt < 4; nt++)
                    mma_tf32(acc[mt][nt], af[mt], bf[nt]);
        }
        __syncthreads();   // single barrier per slab
    }

#pragma unroll
    for (int mt = 0; mt < 2; mt++)
#pragma unroll
        for (int nt = 0; nt < 4; nt++) {
            const int row = m0 + wm + mt * 16 + g;
            const int col = wn + nt * 8 + 2 * tg;
            *(float2*)&C[(size_t)row * HDIM + col]       = make_float2(acc[mt][nt][0], acc[mt][nt][1]);
            *(float2*)&C[(size_t)(row + 8) * HDIM + col] = make_float2(acc[mt][nt][2], acc[mt][nt][3]);
        }
}

// ============================================================================
// Kernel 4: output = LayerNorm(query + context) * gamma + beta (unchanged).
// ============================================================================
__global__ __launch_bounds__(256)
void ln_kernel(const float* __restrict__ query, const float* __restrict__ gamma,
               const float* __restrict__ beta, float* __restrict__ out)
{
    const int row = blockIdx.x;
    const int t   = threadIdx.x;
    const float* qp = query + (size_t)row * DIM;
    const float* cp = g_ctx + (size_t)row * DIM;

    float4 qv = *(const float4*)&qp[t * 4];
    float4 cv = *(const float4*)&cp[t * 4];
    float x0 = qv.x + cv.x, x1 = qv.y + cv.y, x2 = qv.z + cv.z, x3 = qv.w + cv.w;

    __shared__ float red[256];
    red[t] = x0 + x1 + x2 + x3;
    __syncthreads();
#pragma unroll
    for (int s = 128; s > 0; s >>= 1) {
        if (t < s) red[t] += red[t + s];
        __syncthreads();
    }
    const float mu = red[0] * (1.0f / (float)DIM);
    __syncthreads();

    float d0 = x0 - mu, d1 = x1 - mu, d2 = x2 - mu, d3 = x3 - mu;
    red[t] = d0 * d0 + d1 * d1 + d2 * d2 + d3 * d3;
    __syncthreads();
#pragma unroll
    for (int s = 128; s > 0; s >>= 1) {
        if (t < s) red[t] += red[t + s];
        __syncthreads();
    }
    const float rs = rsqrtf(red[0] * (1.0f / (float)DIM) + LN_EPS);

    float4 g4 = *(const float4*)&gamma[t * 4];
    float4 b4 = *(const float4*)&beta[t * 4];
    float4 o  = make_float4(d0 * rs * g4.x + b4.x,
                            d1 * rs * g4.y + b4.y,
                            d2 * rs * g4.z + b4.z,
                            d3 * rs * g4.w + b4.w);
    *(float4*)&out[(size_t)row * DIM + t * 4] = o;
}

// ============================================================================
// Launcher.
// ============================================================================
extern "C" void kernel_launch(void* const* d_in, const int* in_sizes, int n_in,
                              void* d_out, int out_size)
{
    (void)in_sizes; (void)n_in;
    const float* key   = (const float*)d_in[0];
    const float* value = (const float*)d_in[1];
    const float* query = (const float*)d_in[2];
    const float* Wq    = (const float*)d_in[3];
    const float* bq    = (const float*)d_in[4];
    const float* Wk    = (const float*)d_in[5];
    const float* bk    = (const float*)d_in[6];
    const float* Wv    = (const float*)d_in[7];
    const float* bv    = (const float*)d_in[8];
    const float* gamma = (const float*)d_in[9];
    const float* beta  = (const float*)d_in[10];

    float* out = (float*)d_out;
    const long long OUT_ELEMS  = (long long)M_QKV * DIM;
    const long long ATTN_ELEMS = (long long)NHEADS * SEQ * SEQ;
    float* attn_ext = ((long long)out_size >= OUT_ELEMS + ATTN_ELEMS)
                          ? (out + OUT_ELEMS) : nullptr;

    cudaFuncSetAttribute(qkv_tc, cudaFuncAttributeMaxDynamicSharedMemorySize,
                         QKV_SMEM_BYTES);

    dim3 g1(DIM / 128, M_QKV / 128, 3);          // (8, 32, 3)
    qkv_tc<<<g1, 256, QKV_SMEM_BYTES>>>(query, key, value, Wq, Wk, Wv, bq, bk, bv);

    dim3 g2(SEQ / 128, SEQ / 128, NHEADS);       // (8, 8, 64)
    scores_tc<<<g2, 256>>>();

    rowstats_kernel<<<NHEADS * SEQ / 256, 256>>>();

    dim3 g4(1, SEQ / 128, NHEADS);               // (1, 8, 64)
    pv_tc<<<g4, 256>>>(attn_ext);

    ln_kernel<<<M_QKV, 256>>>(query, gamma, beta, out);
}

// round 14
// speedup vs baseline: 1.1800x; 1.0305x over previous
#include <cuda_runtime.h>
#include <cuda_fp16.h>
#include <math.h>
#include <stdint.h>

// B=4, S=1024, D=1024, H=16, DH=64 -> BH=64 heads, per-head Q/K/V = [1024,64] contiguous
#define M_QKV   4096
#define DIM     1024
#define NHEADS  64
#define SEQ     1024
#define HDIM    64
#define SCALE   0.03125f      // D^-0.5
#define LN_EPS  1e-5f

#define SSTR    20            // 16-wide tile stride (qkv/pv): conflict-free frags
#define FSTR    68            // 64-wide tile stride (scores full tile): 68%32==4
#define VSTR    72            // V tile stride: 72%32==8
#define NTILES  8

#define QKV_STAGES 3
#define QKV_SMEM_FLOATS (QKV_STAGES * 2 * 128 * SSTR)
#define QKV_SMEM_BYTES  (QKV_SMEM_FLOATS * 4)           // 61,440 B

// -------------------- scratch (allocation-free: __device__ globals) --------------------
__device__ float  g_q[M_QKV * DIM];
__device__ float  g_k[M_QKV * DIM];
__device__ float  g_v[M_QKV * DIM];
__device__ float  g_ctx[M_QKV * DIM];
__device__ float  g_attn[(size_t)NHEADS * SEQ * SEQ];
__device__ __half g_logit[(size_t)NHEADS * SEQ * SEQ];
__device__ float  g_tmax[(size_t)NHEADS * SEQ * NTILES];
__device__ float  g_tsum[(size_t)NHEADS * SEQ * NTILES];
__device__ float  g_rmax[(size_t)NHEADS * SEQ];
__device__ float  g_rinv[(size_t)NHEADS * SEQ];

// -------------------- mma / async helpers --------------------
// Operands fed as RAW fp32 — HMMA.TF32 truncates low mantissa bits in HW.
__device__ __forceinline__ void mma_tf32(float (&d)[4], const float (&a)[4], const float (&b)[2]) {
    asm volatile(
        "mma.sync.aligned.m16n8k8.row.col.f32.tf32.tf32.f32 "
        "{%0,%1,%2,%3}, {%4,%5,%6,%7}, {%8,%9}, {%0,%1,%2,%3};\n"
        : "+f"(d[0]), "+f"(d[1]), "+f"(d[2]), "+f"(d[3])
        : "r"(__float_as_uint(a[0])), "r"(__float_as_uint(a[1])),
          "r"(__float_as_uint(a[2])), "r"(__float_as_uint(a[3])),
          "r"(__float_as_uint(b[0])), "r"(__float_as_uint(b[1])));
}

__device__ __forceinline__ void cp_async16(uint32_t smem_dst, const void* gmem_src) {
    asm volatile("cp.async.cg.shared.global [%0], [%1], 16;\n"
                 :: "r"(smem_dst), "l"(gmem_src));
}
__device__ __forceinline__ void cp_async_commit() {
    asm volatile("cp.async.commit_group;\n");
}
template <int N>
__device__ __forceinline__ void cp_async_wait() {
    asm volatile("cp.async.wait_group %0;\n" :: "n"(N));
}

__device__ __forceinline__ void softmax_comb(float& m, float& s, float m2, float s2) {
    float M = fmaxf(m, m2);
    s = s * __expf(m - M) + s2 * __expf(m2 - M);
    m = M;
}

// ============================================================================
// Kernel 1: QKV projections — BK=16, 3-stage cp.async pipeline (R12 verbatim).
// ============================================================================
__global__ __launch_bounds__(256, 2)
void qkv_tc(const float* __restrict__ Xq, const float* __restrict__ Xk, const float* __restrict__ Xv,
            const float* __restrict__ Wq, const float* __restrict__ Wk, const float* __restrict__ Wv,
            const float* __restrict__ bq, const float* __restrict__ bk, const float* __restrict__ bv)
{
    extern __shared__ float qsm[];
    const int z = blockIdx.z;
    const float* A    = (z == 0) ? Xq : (z == 1) ? Xk : Xv;
    const float* W    = (z == 0) ? Wq : (z == 1) ? Wk : Wv;
    const float* bias = (z == 0) ? bq : (z == 1) ? bk : bv;
    float*       C    = (z == 0) ? g_q : (z == 1) ? g_k : g_v;

    const int tid  = threadIdx.x;
    const int lane = tid & 31;
    const int warp = tid >> 5;
    const int g    = lane >> 2;
    const int tg   = lane & 3;
    const int wm   = (warp >> 1) * 32;
    const int wn   = (warp & 1) * 64;
    const int m0   = blockIdx.y * 128;
    const int n0   = blockIdx.x * 128;
    const int lr   = tid >> 2;
    const int lc   = (tid & 3) * 4;

    const float* Ap  = A + (size_t)(m0 + lr) * DIM + lc;
    const float* Ap2 = A + (size_t)(m0 + lr + 64) * DIM + lc;
    const float* Wp  = W + (size_t)(n0 + lr) * DIM + lc;
    const float* Wp2 = W + (size_t)(n0 + lr + 64) * DIM + lc;

    uint32_t sA[QKV_STAGES], sB[QKV_STAGES];
#pragma unroll
    for (int s = 0; s < QKV_STAGES; s++) {
        sA[s] = (uint32_t)__cvta_generic_to_shared(qsm + s * 2 * 128 * SSTR + lr * SSTR + lc);
        sB[s] = (uint32_t)__cvta_generic_to_shared(qsm + (s * 2 + 1) * 128 * SSTR + lr * SSTR + lc);
    }
    const uint32_t rowoff = 64 * SSTR * 4;

    float acc[2][8][4];
#pragma unroll
    for (int i = 0; i < 2; i++)
#pragma unroll
        for (int j = 0; j < 8; j++)
#pragma unroll
            for (int q = 0; q < 4; q++) acc[i][j][q] = 0.f;

#pragma unroll
    for (int s = 0; s < 2; s++) {
        const int k = s * 16;
        cp_async16(sA[s],          Ap  + k);
        cp_async16(sA[s] + rowoff, Ap2 + k);
        cp_async16(sB[s],          Wp  + k);
        cp_async16(sB[s] + rowoff, Wp2 + k);
        cp_async_commit();
    }

    const int NIT = DIM / 16;   // 64
    for (int it = 0; it < NIT; it++) {
        cp_async_wait<1>();
        __syncthreads();

        if (it + 2 < NIT) {
            const int k2 = (it + 2) * 16;
            const int nb = (it + 2) % QKV_STAGES;
            cp_async16(sA[nb],          Ap  + k2);
            cp_async16(sA[nb] + rowoff, Ap2 + k2);
            cp_async16(sB[nb],          Wp  + k2);
            cp_async16(sB[nb] + rowoff, Wp2 + k2);
            cp_async_commit();
        }

        const int cb_ = it % QKV_STAGES;
        const float* as = qsm + cb_ * 2 * 128 * SSTR;
        const float* bs = as + 128 * SSTR;
#pragma unroll
        for (int ks = 0; ks < 2; ks++) {
            const int kb = ks * 8;
            float af[2][4];
#pragma unroll
            for (int mt = 0; mt < 2; mt++) {
                const int rb = wm + mt * 16;
                af[mt][0] = as[(rb + g) * SSTR + kb + tg];
                af[mt][1] = as[(rb + g + 8) * SSTR + kb + tg];
                af[mt][2] = as[(rb + g) * SSTR + kb + tg + 4];
                af[mt][3] = as[(rb + g + 8) * SSTR + kb + tg + 4];
            }
            float bf[8][2];
#pragma unroll
            for (int nt = 0; nt < 8; nt++) {
                const int cb = wn + nt * 8;
                bf[nt][0] = bs[(cb + g) * SSTR + kb + tg];
                bf[nt][1] = bs[(cb + g) * SSTR + kb + tg + 4];
            }
#pragma unroll
            for (int mt = 0; mt < 2; mt++)
#pragma unroll
                for (int nt = 0; nt < 8; nt++)
                    mma_tf32(acc[mt][nt], af[mt], bf[nt]);
        }
    }

#pragma unroll
    for (int mt = 0; mt < 2; mt++)
#pragma unroll
        for (int nt = 0; nt < 8; nt++) {
            const int row = m0 + wm + mt * 16 + g;
            const int col = n0 + wn + nt * 8 + 2 * tg;
            const float bx = bias[col], by = bias[col + 1];
            float2 o0 = make_float2(acc[mt][nt][0] + bx, acc[mt][nt][1] + by);
            float2 o1 = make_float2(acc[mt][nt][2] + bx, acc[mt][nt][3] + by);
            *(float2*)&C[(size_t)row * DIM + col]       = o0;
            *(float2*)&C[(size_t)(row + 8) * DIM + col] = o1;
        }
}

// ============================================================================
// Kernel 2: scores — FULL 128x64 Q/K tiles, single barrier (R13 verbatim).
// ============================================================================
__global__ __launch_bounds__(256, 2)
void scores_tc()
{
    __shared__ float As[128 * FSTR];
    __shared__ float Bs[128 * FSTR];
    __shared__ float sm_m[128][2];
    __shared__ float sm_s[128][2];

    const int bh = blockIdx.z;
    const float* Q = g_q + (size_t)bh * SEQ * HDIM;
    const float* K = g_k + (size_t)bh * SEQ * HDIM;
    __half*      L = g_logit + (size_t)bh * SEQ * SEQ;

    const int tid  = threadIdx.x;
    const int lane = tid & 31;
    const int warp = tid >> 5;
    const int g    = lane >> 2;
    const int tg   = lane & 3;
    const int wm   = (warp >> 1) * 32;
    const int wn   = (warp & 1) * 64;
    const int wn_half = warp & 1;
    const int m0   = blockIdx.y * 128;
    const int n0   = blockIdx.x * 128;
    const int lr   = tid >> 2;
    const int lc   = (tid & 3) * 4;

    const float* Qp  = Q + (size_t)(m0 + lr) * HDIM + lc;
    const float* Qp2 = Q + (size_t)(m0 + lr + 64) * HDIM + lc;
    const float* Kp  = K + (size_t)(n0 + lr) * HDIM + lc;
    const float* Kp2 = K + (size_t)(n0 + lr + 64) * HDIM + lc;
#pragma unroll
    for (int ko = 0; ko < HDIM; ko += 16) {
        *(float4*)&As[lr * FSTR + ko + lc]        = *(const float4*)(Qp  + ko);
        *(float4*)&As[(lr + 64) * FSTR + ko + lc] = *(const float4*)(Qp2 + ko);
        *(float4*)&Bs[lr * FSTR + ko + lc]        = *(const float4*)(Kp  + ko);
        *(float4*)&Bs[(lr + 64) * FSTR + ko + lc] = *(const float4*)(Kp2 + ko);
    }
    __syncthreads();

    float acc[2][8][4];
#pragma unroll
    for (int i = 0; i < 2; i++)
#pragma unroll
        for (int j = 0; j < 8; j++)
#pragma unroll
            for (int q = 0; q < 4; q++) acc[i][j][q] = 0.f;

#pragma unroll
    for (int ks = 0; ks < 8; ks++) {
        const int kb = ks * 8;
        float af[2][4];
#pragma unroll
        for (int mt = 0; mt < 2; mt++) {
            const int rb = wm + mt * 16;
            af[mt][0] = As[(rb + g) * FSTR + kb + tg];
            af[mt][1] = As[(rb + g + 8) * FSTR + kb + tg];
            af[mt][2] = As[(rb + g) * FSTR + kb + tg + 4];
            af[mt][3] = As[(rb + g + 8) * FSTR + kb + tg + 4];
        }
        float bf[8][2];
#pragma unroll
        for (int nt = 0; nt < 8; nt++) {
            const int cb = wn + nt * 8;
            bf[nt][0] = Bs[(cb + g) * FSTR + kb + tg];
            bf[nt][1] = Bs[(cb + g) * FSTR + kb + tg + 4];
        }
#pragma unroll
        for (int mt = 0; mt < 2; mt++)
#pragma unroll
            for (int nt = 0; nt < 8; nt++)
                mma_tf32(acc[mt][nt], af[mt], bf[nt]);
    }

#pragma unroll
    for (int mt = 0; mt < 2; mt++)
#pragma unroll
        for (int nt = 0; nt < 8; nt++)
#pragma unroll
            for (int q = 0; q < 4; q++) acc[mt][nt][q] *= SCALE;

#pragma unroll
    for (int mt = 0; mt < 2; mt++)
#pragma unroll
        for (int nt = 0; nt < 8; nt++) {
            const int row = m0 + wm + mt * 16 + g;
            const int col = n0 + wn + nt * 8 + 2 * tg;
            *(__half2*)&L[(size_t)row * SEQ + col]       = __floats2half2_rn(acc[mt][nt][0], acc[mt][nt][1]);
            *(__half2*)&L[(size_t)(row + 8) * SEQ + col] = __floats2half2_rn(acc[mt][nt][2], acc[mt][nt][3]);
        }

#pragma unroll
    for (int mt = 0; mt < 2; mt++) {
#pragma unroll
        for (int h = 0; h < 2; h++) {
            const int q0 = h * 2;
            float m = -3.4e38f;
#pragma unroll
            for (int nt = 0; nt < 8; nt++)
                m = fmaxf(m, fmaxf(acc[mt][nt][q0], acc[mt][nt][q0 + 1]));
            float s = 0.f;
#pragma unroll
            for (int nt = 0; nt < 8; nt++)
                s += __expf(acc[mt][nt][q0] - m) + __expf(acc[mt][nt][q0 + 1] - m);
#pragma unroll
            for (int off = 1; off <= 2; off <<= 1) {
                float mo = __shfl_xor_sync(0xffffffffu, m, off);
                float so = __shfl_xor_sync(0xffffffffu, s, off);
                softmax_comb(m, s, mo, so);
            }
            if (tg == 0) {
                const int r = wm + mt * 16 + h * 8 + g;
                sm_m[r][wn_half] = m;
                sm_s[r][wn_half] = s;
            }
        }
    }
    __syncthreads();

    if (tid < 128) {
        float m = sm_m[tid][0], s = sm_s[tid][0];
        softmax_comb(m, s, sm_m[tid][1], sm_s[tid][1]);
        const size_t idx = ((size_t)bh * SEQ + m0 + tid) * NTILES + blockIdx.x;
        g_tmax[idx] = m;
        g_tsum[idx] = s;
    }
}

// ============================================================================
// Kernel 2b: fold per-tile stats into per-row (max, 1/sum).
// ============================================================================
__global__ __launch_bounds__(256)
void rowstats_kernel()
{
    const int row = blockIdx.x * 256 + threadIdx.x;
    const float* tm = &g_tmax[(size_t)row * NTILES];
    const float* ts = &g_tsum[(size_t)row * NTILES];
    float m = tm[0], s = ts[0];
#pragma unroll
    for (int t = 1; t < NTILES; t++)
        softmax_comb(m, s, tm[t], ts[t]);
    g_rmax[row] = m;
    g_rinv[row] = 1.0f / s;
}

// ============================================================================
// Kernel 3: pv — R12 verbatim (BK=16, register prefetch, two syncs/slab;
// measured 144.5us vs 155.7 for the single-sync variant — reverted).
// ============================================================================
__global__ __launch_bounds__(256, 2)
void pv_tc(float* attn_ext)
{
    float* attn = attn_ext ? attn_ext : g_attn;

    __shared__ float Ps[128 * SSTR];
    __shared__ float Vs[16 * VSTR];

    const int bh = blockIdx.z;
    float*        P  = attn    + (size_t)bh * SEQ * SEQ;
    const __half* Lh = g_logit + (size_t)bh * SEQ * SEQ;
    const float*  V  = g_v     + (size_t)bh * SEQ * HDIM;
    float*        C  = g_ctx   + (size_t)bh * SEQ * HDIM;

    const int tid  = threadIdx.x;
    const int lane = tid & 31;
    const int warp = tid >> 5;
    const int g    = lane >> 2;
    const int tg   = lane & 3;
    const int wm   = (warp >> 1) * 32;
    const int wn   = (warp & 1) * 32;
    const int m0   = blockIdx.y * 128;
    const int lr   = tid >> 2;
    const int lc   = (tid & 3) * 4;
    const int vr   = tid >> 4;
    const int vc   = (tid & 15) * 4;

    const __half* Lp  = Lh + (size_t)(m0 + lr) * SEQ + lc;
    const __half* Lp2 = Lh + (size_t)(m0 + lr + 64) * SEQ + lc;
    float* Pp  = P + (size_t)(m0 + lr) * SEQ + lc;
    float* Pp2 = P + (size_t)(m0 + lr + 64) * SEQ + lc;
    const float* Vp = V + (size_t)vr * HDIM + vc;

    const size_t rbase = (size_t)bh * SEQ + m0;
    const float rm0 = g_rmax[rbase + lr],      ri0 = g_rinv[rbase + lr];
    const float rm1 = g_rmax[rbase + lr + 64], ri1 = g_rinv[rbase + lr + 64];

    float acc[2][4][4];
#pragma unroll
    for (int i = 0; i < 2; i++)
#pragma unroll
        for (int j = 0; j < 4; j++)
#pragma unroll
            for (int q = 0; q < 4; q++) acc[i][j][q] = 0.f;

    uint2 rl0 = __ldcs((const uint2*)(Lp));
    uint2 rl1 = __ldcs((const uint2*)(Lp2));
    float4 rv = *(const float4*)(Vp);

    for (int k0 = 0; k0 < SEQ; k0 += 16) {
        float2 a0 = __half22float2(*(__half2*)&rl0.x);
        float2 a1 = __half22float2(*(__half2*)&rl0.y);
        float2 b0 = __half22float2(*(__half2*)&rl1.x);
        float2 b1 = __half22float2(*(__half2*)&rl1.y);

        float4 p0, p1;
        p0.x = __expf(a0.x - rm0) * ri0; p0.y = __expf(a0.y - rm0) * ri0;
        p0.z = __expf(a1.x - rm0) * ri0; p0.w = __expf(a1.y - rm0) * ri0;
        p1.x = __expf(b0.x - rm1) * ri1; p1.y = __expf(b0.y - rm1) * ri1;
        p1.z = __expf(b1.x - rm1) * ri1; p1.w = __expf(b1.y - rm1) * ri1;

        __stcs((float4*)(Pp  + k0), p0);
        __stcs((float4*)(Pp2 + k0), p1);

        *(float4*)&Ps[lr * SSTR + lc]        = p0;
        *(float4*)&Ps[(lr + 64) * SSTR + lc] = p1;
        *(float4*)&Vs[vr * VSTR + vc]        = rv;
        __syncthreads();

        if (k0 + 16 < SEQ) {
            rl0 = __ldcs((const uint2*)(Lp  + k0 + 16));
            rl1 = __ldcs((const uint2*)(Lp2 + k0 + 16));
            rv  = *(const float4*)(Vp + (size_t)(k0 + 16) * HDIM);
        }

#pragma unroll
        for (int ks = 0; ks < 2; ks++) {
            const int kb = ks * 8;
            float af[2][4];
#pragma unroll
            for (int mt = 0; mt < 2; mt++) {
                const int rb = wm + mt * 16;
                af[mt][0] = Ps[(rb + g) * SSTR + kb + tg];
                af[mt][1] = Ps[(rb + g + 8) * SSTR + kb + tg];
                af[mt][2] = Ps[(rb + g) * SSTR + kb + tg + 4];
                af[mt][3] = Ps[(rb + g + 8) * SSTR + kb + tg + 4];
            }
            float bf[4][2];
#pragma unroll
            for (int nt = 0; nt < 4; nt++) {
                const int cb = wn + nt * 8;
                bf[nt][0] = Vs[(kb + tg) * VSTR + cb + g];
                bf[nt][1] = Vs[(kb + tg + 4) * VSTR + cb + g];
            }
#pragma unroll
            for (int mt = 0; mt < 2; mt++)
#pragma unroll
                for (int nt = 0; nt < 4; nt++)
                    mma_tf32(acc[mt][nt], af[mt], bf[nt]);
        }
        __syncthreads();
    }

#pragma unroll
    for (int mt = 0; mt < 2; mt++)
#pragma unroll
        for (int nt = 0; nt < 4; nt++) {
            const int row = m0 + wm + mt * 16 + g;
            const int col = wn + nt * 8 + 2 * tg;
            *(float2*)&C[(size_t)row * HDIM + col]       = make_float2(acc[mt][nt][0], acc[mt][nt][1]);
            *(float2*)&C[(size_t)(row + 8) * HDIM + col] = make_float2(acc[mt][nt][2], acc[mt][nt][3]);
        }
}

// ============================================================================
// Kernel 4: output = LayerNorm(query + context) * gamma + beta (unchanged).
// ============================================================================
__global__ __launch_bounds__(256)
void ln_kernel(const float* __restrict__ query, const float* __restrict__ gamma,
               const float* __restrict__ beta, float* __restrict__ out)
{
    const int row = blockIdx.x;
    const int t   = threadIdx.x;
    const float* qp = query + (size_t)row * DIM;
    const float* cp = g_ctx + (size_t)row * DIM;

    float4 qv = *(const float4*)&qp[t * 4];
    float4 cv = *(const float4*)&cp[t * 4];
    float x0 = qv.x + cv.x, x1 = qv.y + cv.y, x2 = qv.z + cv.z, x3 = qv.w + cv.w;

    __shared__ float red[256];
    red[t] = x0 + x1 + x2 + x3;
    __syncthreads();
#pragma unroll
    for (int s = 128; s > 0; s >>= 1) {
        if (t < s) red[t] += red[t + s];
        __syncthreads();
    }
    const float mu = red[0] * (1.0f / (float)DIM);
    __syncthreads();

    float d0 = x0 - mu, d1 = x1 - mu, d2 = x2 - mu, d3 = x3 - mu;
    red[t] = d0 * d0 + d1 * d1 + d2 * d2 + d3 * d3;
    __syncthreads();
#pragma unroll
    for (int s = 128; s > 0; s >>= 1) {
        if (t < s) red[t] += red[t + s];
        __syncthreads();
    }
    const float rs = rsqrtf(red[0] * (1.0f / (float)DIM) + LN_EPS);

    float4 g4 = *(const float4*)&gamma[t * 4];
    float4 b4 = *(const float4*)&beta[t * 4];
    float4 o  = make_float4(d0 * rs * g4.x + b4.x,
                            d1 * rs * g4.y + b4.y,
                            d2 * rs * g4.z + b4.z,
                            d3 * rs * g4.w + b4.w);
    *(float4*)&out[(size_t)row * DIM + t * 4] = o;
}

// ============================================================================
// Launcher.
// ============================================================================
extern "C" void kernel_launch(void* const* d_in, const int* in_sizes, int n_in,
                              void* d_out, int out_size)
{
    (void)in_sizes; (void)n_in;
    const float* key   = (const float*)d_in[0];
    const float* value = (const float*)d_in[1];
    const float* query = (const float*)d_in[2];
    const float* Wq    = (const float*)d_in[3];
    const float* bq    = (const float*)d_in[4];
    const float* Wk    = (const float*)d_in[5];
    const float* bk    = (const float*)d_in[6];
    const float* Wv    = (const float*)d_in[7];
    const float* bv    = (const float*)d_in[8];
    const float* gamma = (const float*)d_in[9];
    const float* beta  = (const float*)d_in[10];

    float* out = (float*)d_out;
    const long long OUT_ELEMS  = (long long)M_QKV * DIM;
    const long long ATTN_ELEMS = (long long)NHEADS * SEQ * SEQ;
    float* attn_ext = ((long long)out_size >= OUT_ELEMS + ATTN_ELEMS)
                          ? (out + OUT_ELEMS) : nullptr;

    cudaFuncSetAttribute(qkv_tc, cudaFuncAttributeMaxDynamicSharedMemorySize,
                         QKV_SMEM_BYTES);

    dim3 g1(DIM / 128, M_QKV / 128, 3);          // (8, 32, 3)
    qkv_tc<<<g1, 256, QKV_SMEM_BYTES>>>(query, key, value, Wq, Wk, Wv, bq, bk, bv);

    dim3 g2(SEQ / 128, SEQ / 128, NHEADS);       // (8, 8, 64)
    scores_tc<<<g2, 256>>>();

    rowstats_kernel<<<NHEADS * SEQ / 256, 256>>>();

    dim3 g4(1, SEQ / 128, NHEADS);               // (1, 8, 64)
    pv_tc<<<g4, 256>>>(attn_ext);

    ln_kernel<<<M_QKV, 256>>>(query, gamma, beta, out);
}